// round 17
// baseline (speedup 1.0000x reference)
#include <cuda_runtime.h>
#include <cstdint>

#define En 64
#define An 8
#define Ln 2048
#define Dn 128
#define Hn 8
#define DKn 16
#define EA 512
#define SPLIT 8
#define RPS 256
#define TLC 32             // CTA tile rows (4 warps x 8)
#define WSTR 132           // padded row stride inside a warp tile (floats)
#define WTILE (2 * 8 * WSTR)   // 2112 floats per warp (two 8-row buffers)

typedef unsigned long long ull;

__device__ __forceinline__ ull fma2(ull a, ull b, ull c) {
    ull d; asm("fma.rn.f32x2 %0, %1, %2, %3;" : "=l"(d) : "l"(a), "l"(b), "l"(c)); return d;
}
__device__ __forceinline__ ull mul2(ull a, ull b) {
    ull d; asm("mul.rn.f32x2 %0, %1, %2;" : "=l"(d) : "l"(a), "l"(b)); return d;
}
__device__ __forceinline__ ull pack2(float x, float y) {
    ull r; asm("mov.b64 %0, {%1,%2};" : "=l"(r) : "f"(x), "f"(y)); return r;
}
__device__ __forceinline__ float2 unpack2(ull v) {
    float2 r; asm("mov.b64 {%0,%1}, %2;" : "=f"(r.x), "=f"(r.y) : "l"(v)); return r;
}
__device__ __forceinline__ float ex2(float x) {
    float y; asm("ex2.approx.ftz.f32 %0, %1;" : "=f"(y) : "f"(x)); return y;
}

__device__ __align__(16) float g_bq[En * Dn];              // agent-independent base query
__device__ __align__(16) float g_Gk[Hn * Dn * DKn];        // SC * (Wk_proj @ Wk[h])
__device__ __align__(16) float g_Rk[EA * Hn * Dn];
__device__ __align__(16) float g_part[EA * SPLIT * 1040];  // m[8],Z[8],w[8][128]
__device__ int g_cnt[EA];

// ---------------- Kernel A: per-e base query (blocks 0..63) + Gk build (64..71) -----------
__global__ void prepA(const float* __restrict__ gc, const float* __restrict__ dep,
                      const float* __restrict__ tbd, const float* __restrict__ Wqp,
                      const float* __restrict__ Wk, const float* __restrict__ Wkp) {
    __shared__ float red[512];
    int blk = blockIdx.x, t = threadIdx.x;  // 512 threads
    if (blk < En) {
        int e = blk, out = t & 127, g = t >> 7;   // 4-way split over input index
        const float* s0 = gc + e * Dn;
        const float* s1 = dep + e * Dn;
        const float* s2 = tbd + e * Dn;
        float a0 = 0.f, a1 = 0.f, a2 = 0.f;
#pragma unroll 8
        for (int ii = 0; ii < 32; ii++) {
            int i = 32 * g + ii;
            a0 += s0[i] * Wqp[i * Dn + out];
            a1 += s1[i] * Wqp[(Dn + i) * Dn + out];
            a2 += s2[i] * Wqp[(2 * Dn + i) * Dn + out];
        }
        red[g * 128 + out] = (a0 + a1) + a2;
        __syncthreads();
        if (t < 128) g_bq[e * Dn + t] = (red[t] + red[128 + t]) + (red[256 + t] + red[384 + t]);
    } else {
        // Gk[h][i][k] = SC * sum_d Wkp[i,d] * Wk[h,d,k]; thread (i = t>>2, qr = t&3)
        __shared__ float wks[Dn * DKn];
        int h = blk - En;
        for (int j = t; j < Dn * DKn; j += 512) wks[j] = Wk[h * Dn * DKn + j];
        __syncthreads();
        int i = t >> 2, qr = t & 3;
        const float* wrow = Wkp + i * Dn + 32 * qr;
        float acc[DKn];
#pragma unroll
        for (int k = 0; k < DKn; k++) acc[k] = 0.f;
#pragma unroll
        for (int p = 0; p < 8; p++) {
            float4 v = *(const float4*)(wrow + 4 * p);
            const float* w0 = wks + (32 * qr + 4 * p) * DKn;
#pragma unroll
            for (int k = 0; k < DKn; k++)
                acc[k] += v.x * w0[k] + v.y * w0[DKn + k] + v.z * w0[2 * DKn + k] + v.w * w0[3 * DKn + k];
        }
#pragma unroll
        for (int k = 0; k < DKn; k++) {
            acc[k] += __shfl_xor_sync(0xffffffffu, acc[k], 1);
            acc[k] += __shfl_xor_sync(0xffffffffu, acc[k], 2);
        }
        if (qr == 0) {
            const float SC = 0.25f * 1.4426950408889634f;
            float* dst = g_Gk + (h * Dn + i) * DKn;
#pragma unroll
            for (int k = 0; k < DKn; k++) dst[k] = SC * acc[k];
        }
    }
}

// ---------------- Kernel B: per-(e,a): q -> qh -> Rk (via Gk) ----------------
__global__ void prepB(const float* __restrict__ loadv, const float* __restrict__ Wqp,
                      const float* __restrict__ Wq) {
    __shared__ float qsm[Dn];
    __shared__ float qhs[Hn * DKn];
    int b = blockIdx.x, e = b >> 3, a = b & 7, t = threadIdx.x;  // 128 threads

    qsm[t] = g_bq[e * Dn + t] + loadv[e * An + a] * Wqp[384 * Dn + t]
           + (float)a * Wqp[385 * Dn + t];
    __syncthreads();
    {
        int h = t >> 4, k = t & 15;
        float acc = 0.f;
#pragma unroll 4
        for (int d = 0; d < Dn; d++) acc += qsm[d] * Wq[(h * Dn + d) * DKn + k];
        qhs[t] = acc;
    }
    __syncthreads();
    {
        int i = t;
#pragma unroll
        for (int h = 0; h < Hn; h++) {
            const float* gk = g_Gk + (h * Dn + i) * DKn;
            const float* qh = qhs + h * DKn;
            float s = 0.f;
#pragma unroll
            for (int k = 0; k < DKn; k++) s += qh[k] * gk[k];
            g_Rk[((size_t)b * Hn + h) * Dn + i] = s;
        }
    }
}

// ---------------- Kernel 2: main. 128 thr, occ 5, per-lane-head accumulation --------------
// smem floats: [0,8448) 4 warp-tiles | sMZ 4x16 @8448 | total 8512 floats (34KB)
#define SM_MZ 8448
#define SMEM_BYTES (8512 * 4)

__global__ __launch_bounds__(128, 5)
void decoder_main(const float* __restrict__ emb, const int* __restrict__ lens,
                  const float* __restrict__ Wvp, const float* __restrict__ Wv,
                  const float* __restrict__ Wo, float* __restrict__ out) {
    extern __shared__ float sm[];
    __shared__ int sflag;

    int blk = blockIdx.x, b = blk >> 3, sp = blk & 7, t = threadIdx.x;
    int wrp = t >> 5, lane = t & 31;
    int h = lane & 7, q = lane >> 3;
    int len = lens[b];
    int cnt = min(len - sp * RPS, RPS);
    int ntiles = (cnt > 0) ? ((cnt + TLC - 1) >> 5) : 0;
    const float* embp = emb + (size_t)b * (Ln * Dn) + (size_t)sp * RPS * Dn;

    float* wbuf = sm + wrp * WTILE;
    float* sMZ  = sm + SM_MZ;
    uint32_t wdst = (uint32_t)__cvta_generic_to_shared(wbuf) + (uint32_t)lane * 16;

    // Rk registers: lane (h,q) holds floats {16j+4q..+3} of head h
    ull rk[16];
    {
        const float* rbase = g_Rk + ((size_t)b * Hn + h) * Dn + 4 * q;
#pragma unroll
        for (int j = 0; j < 8; j++) {
            ulonglong2 v = *(const ulonglong2*)(rbase + 16 * j);
            rk[2 * j] = v.x; rk[2 * j + 1] = v.y;
        }
    }

    float m = -30000.f, Z = 0.f;
    // V accumulator: head h, positions {16j+4q..+3} (same layout as rk)
    ull w[16];
#pragma unroll
    for (int i = 0; i < 16; i++) w[i] = 0ull;

#define LD_STRIPE(tt, bufk)                                                              \
    do {                                                                                  \
        const float* _s = embp + (size_t)((tt) * TLC + wrp * 8) * Dn + lane * 4;          \
        uint32_t _d = wdst + (uint32_t)(bufk) * (8 * WSTR * 4);                           \
        _Pragma("unroll")                                                                 \
        for (int _i = 0; _i < 8; _i++)                                                    \
            asm volatile("cp.async.cg.shared.global [%0], [%1], 16;\n"                    \
                         :: "r"(_d + _i * (WSTR * 4)), "l"(_s + _i * Dn) : "memory");     \
        asm volatile("cp.async.commit_group;\n" ::: "memory");                            \
    } while (0)

    if (ntiles > 0) {
        LD_STRIPE(0, 0);
        if (ntiles > 1) LD_STRIPE(1, 1);

        for (int tt = 0; tt < ntiles; tt++) {
            if (tt + 1 < ntiles) asm volatile("cp.async.wait_group 1;\n" ::: "memory");
            else                 asm volatile("cp.async.wait_group 0;\n" ::: "memory");
            __syncwarp();
            const float* tb = wbuf + (tt & 1) * (8 * WSTR);
            int base = tt * TLC + wrp * 8;

            // score: 8 rows; lane (h,q); full dot after 2 shfls
            float s8[8];
#pragma unroll
            for (int i = 0; i < 8; i++) {
                const ulonglong2* rp = (const ulonglong2*)(tb + i * WSTR + 4 * q);
                ull a0 = 0ull, a1 = 0ull;
#pragma unroll
                for (int j = 0; j < 8; j++) {
                    ulonglong2 ev = rp[4 * j];
                    a0 = fma2(ev.x, rk[2 * j], a0);
                    a1 = fma2(ev.y, rk[2 * j + 1], a1);
                }
                float2 fa = unpack2(a0), fb = unpack2(a1);
                float sv = (fa.x + fa.y) + (fb.x + fb.y);
                sv += __shfl_xor_sync(0xffffffffu, sv, 8);
                sv += __shfl_xor_sync(0xffffffffu, sv, 16);
                s8[i] = (base + i < cnt) ? sv : -1e30f;
            }

            // per-lane online softmax for head h (dup over q)
            float tm = s8[0];
#pragma unroll
            for (int i = 1; i < 8; i++) tm = fmaxf(tm, s8[i]);
            float mn = fmaxf(m, tm);
            float f = ex2(m - mn);
            m = mn;
            float zs = 0.f;
#pragma unroll
            for (int i = 0; i < 8; i++) {
                s8[i] = (s8[i] > -1e29f) ? ex2(s8[i] - mn) : 0.f;
                zs += s8[i];
            }
            Z = Z * f + zs;

            // rescale (f per-lane, no shfl)
            {
                ull fp = pack2(f, f);
#pragma unroll
                for (int j = 0; j < 16; j++) w[j] = mul2(w[j], fp);
            }
            // accumulate: p in registers; same broadcast-friendly read as score
#pragma unroll
            for (int i = 0; i < 8; i++) {
                const ulonglong2* rp = (const ulonglong2*)(tb + i * WSTR + 4 * q);
                ull pp = pack2(s8[i], s8[i]);
#pragma unroll
                for (int j = 0; j < 8; j++) {
                    ulonglong2 ev = rp[4 * j];
                    w[2 * j]     = fma2(pp, ev.x, w[2 * j]);
                    w[2 * j + 1] = fma2(pp, ev.y, w[2 * j + 1]);
                }
            }
            __syncwarp();
            if (tt + 2 < ntiles) LD_STRIPE(tt + 2, tt & 1);
        }
    }

    // ---- CTA merge of 4 per-warp partials ----
    if (q == 0) { sMZ[wrp * 16 + h] = m; sMZ[wrp * 16 + 8 + h] = Z; }
    __syncthreads();
    {
        // store lane's w into [wrp*8+h][128] container at positions 16j+4q
        float* Wmf = sm;
#pragma unroll
        for (int j = 0; j < 8; j++) {
            ulonglong2 v; v.x = w[2 * j]; v.y = w[2 * j + 1];
            *(ulonglong2*)(Wmf + (wrp * 8 + h) * 128 + 16 * j + 4 * q) = v;
        }
    }
    __syncthreads();
    {
        int h2 = t >> 4, g = t & 15;  // head, 2 quads each
        float mc = sMZ[h2];
#pragma unroll
        for (int wv = 1; wv < 4; wv++) mc = fmaxf(mc, sMZ[wv * 16 + h2]);
        float fw[4], Zc = 0.f;
#pragma unroll
        for (int wv = 0; wv < 4; wv++) {
            fw[wv] = ex2(sMZ[wv * 16 + h2] - mc);
            Zc += sMZ[wv * 16 + 8 + h2] * fw[wv];
        }
        const float4* Wmf = (const float4*)sm;
        float* gp = g_part + (size_t)blk * 1040;
#pragma unroll
        for (int part = 0; part < 2; part++) {
            int dq = g + 16 * part;
            float4 acc = make_float4(0.f, 0.f, 0.f, 0.f);
#pragma unroll
            for (int wv = 0; wv < 4; wv++) {
                float4 v = Wmf[(wv * 8 + h2) * 32 + dq];
                acc.x += fw[wv] * v.x; acc.y += fw[wv] * v.y;
                acc.z += fw[wv] * v.z; acc.w += fw[wv] * v.w;
            }
            *(float4*)(gp + 16 + h2 * Dn + 4 * dq) = acc;
        }
        if (g == 0) { gp[h2] = mc; gp[8 + h2] = Zc; }
    }
    __syncthreads();

    // ---- last-arriver combine + epilogue ----
    __threadfence();
    if (t == 0) {
        int r = atomicAdd(&g_cnt[b], 1);
        sflag = (r == SPLIT - 1);
        if (r == SPLIT - 1) g_cnt[b] = 0;
    }
    __syncthreads();
    if (!sflag) return;
    __threadfence();

    int a = b & 7;
    float* cc   = sm;
    float* wfs  = sm + 64;
    float* vmid = sm + 64 + Hn * Dn;
    float* sCtx = vmid + Hn * Dn;
    const float* Pb = g_part + (size_t)(b * SPLIT) * 1040;

    if (t < 8) {
        float mm = -1e30f;
#pragma unroll
        for (int s = 0; s < SPLIT; s++) mm = fmaxf(mm, Pb[s * 1040 + t]);
        float as[SPLIT], Zt = 0.f;
#pragma unroll
        for (int s = 0; s < SPLIT; s++) {
            as[s] = ex2(Pb[s * 1040 + t] - mm);
            Zt += Pb[s * 1040 + 8 + t] * as[s];
        }
        float inv = 1.f / Zt;
#pragma unroll
        for (int s = 0; s < SPLIT; s++) cc[s * 8 + t] = as[s] * inv;
    }
    __syncthreads();
    {
#pragma unroll
        for (int hh = 0; hh < Hn; hh++) {
            int off = 16 + hh * Dn + t;
            float acc = 0.f;
#pragma unroll
            for (int s = 0; s < SPLIT; s++) acc += Pb[s * 1040 + off] * cc[s * 8 + hh];
            wfs[hh * Dn + t] = acc;
        }
    }
    __syncthreads();
    {
        float acc[Hn];
        float bias = (float)a * Wvp[Dn * Dn + t];
#pragma unroll
        for (int hh = 0; hh < Hn; hh++) acc[hh] = bias;
#pragma unroll 4
        for (int i = 0; i < Dn; i++) {
            float wv = Wvp[i * Dn + t];
#pragma unroll
            for (int hh = 0; hh < Hn; hh++) acc[hh] += wfs[hh * Dn + i] * wv;
        }
#pragma unroll
        for (int hh = 0; hh < Hn; hh++) vmid[hh * Dn + t] = acc[hh];
    }
    __syncthreads();
    {
        int hh = t >> 4, k = t & 15;
        const float* wvr = Wv + hh * Dn * DKn + k;
        const float* vm = vmid + hh * Dn;
        float acc = 0.f;
#pragma unroll 4
        for (int d = 0; d < Dn; d++) acc += vm[d] * wvr[d * DKn];
        sCtx[t] = acc;
    }
    __syncthreads();
    {
        float acc = 0.f;
#pragma unroll 4
        for (int j = 0; j < Hn * DKn; j++) acc += sCtx[j] * Wo[j * Dn + t];
        out[(size_t)b * Dn + t] = acc;
    }
}

// ---------------------------------------------------------------------------
extern "C" void kernel_launch(void* const* d_in, const int* in_sizes, int n_in,
                              void* d_out, int out_size) {
    const float* gc      = (const float*)d_in[0];
    const float* depot   = (const float*)d_in[1];
    const float* tbd     = (const float*)d_in[2];
    const float* loadv   = (const float*)d_in[3];
    const float* emb     = (const float*)d_in[4];
    const int*   lens    = (const int*)  d_in[5];
    const float* Wq_proj = (const float*)d_in[6];
    const float* Wk_proj = (const float*)d_in[7];
    const float* Wv_proj = (const float*)d_in[8];
    const float* Wq      = (const float*)d_in[9];
    const float* Wk      = (const float*)d_in[10];
    const float* Wv      = (const float*)d_in[11];
    const float* Wo      = (const float*)d_in[12];
    float* out = (float*)d_out;

    prepA<<<En + Hn, 512>>>(gc, depot, tbd, Wq_proj, Wk, Wk_proj);
    prepB<<<EA, 128>>>(loadv, Wq_proj, Wq);

    cudaFuncSetAttribute(decoder_main, cudaFuncAttributeMaxDynamicSharedMemorySize, SMEM_BYTES);
    decoder_main<<<EA * SPLIT, 128, SMEM_BYTES>>>(emb, lens, Wv_proj, Wv, Wo, out);
}